// round 1
// baseline (speedup 1.0000x reference)
#include <cuda_runtime.h>
#include <stdint.h>

#define NB 32
#define HH 512
#define WW 512
#define WPR 16  // 512 bits / 32 = 16 words per row

// Accumulator slots per batch:
// 0: S_p   1: S_pg
// 2: pe_c  3: pm_c  4: pj_c  5: ge_c  6: gm_c  7: gj_c
// 8: Ie    9: Im   10: Ij
// 11: medsum_p2g  12: medsum_g2p  13: N_p  14: N_g
__device__ float g_acc[NB][16];
__device__ uint32_t g_pmask[NB][HH][WPR];
__device__ uint32_t g_gmask[NB][HH][WPR];

__global__ void k0_zero() {
    int i = threadIdx.x;
    if (i < NB * 16) ((float*)g_acc)[i] = 0.0f;
}

__global__ void __launch_bounds__(256) k1_pixel(const float* __restrict__ pred,
                                                const float* __restrict__ gt) {
    const int x = blockIdx.x * 32 + threadIdx.x;
    const int y = blockIdx.y * 8 + threadIdx.y;
    const int b = blockIdx.z;
    const size_t base = (size_t)b * (HH * WW);

    float p[3][3], g[3][3];
#pragma unroll
    for (int dy = 0; dy < 3; dy++) {
        int yy = y + dy - 1;
        bool yok = ((unsigned)yy < HH);
#pragma unroll
        for (int dx = 0; dx < 3; dx++) {
            int xx = x + dx - 1;
            bool ok = yok && ((unsigned)xx < WW);
            size_t off = base + (size_t)yy * WW + xx;
            p[dy][dx] = ok ? __ldg(pred + off) : 0.0f;
            g[dy][dx] = ok ? __ldg(gt + off) : 0.0f;
        }
    }

    const float pc = p[1][1], gc = g[1][1];
    const float np = p[0][0] + p[0][1] + p[0][2] + p[1][0] + p[1][2] + p[2][0] + p[2][1] + p[2][2];
    const float ng = g[0][0] + g[0][1] + g[0][2] + g[1][0] + g[1][2] + g[2][0] + g[2][1] + g[2][2];

    const bool pon = pc > 0.5f;
    const bool gon = gc > 0.5f;

    const float pe = (pon && np == 1.0f) ? 1.0f : 0.0f;
    const float pm = (pon && np == 2.0f) ? 1.0f : 0.0f;
    const float pj = (pon && np > 2.0f) ? 1.0f : 0.0f;
    const float ge = (gon && ng == 1.0f) ? 1.0f : 0.0f;
    const float gm = (gon && ng == 2.0f) ? 1.0f : 0.0f;
    const float gj = (gon && ng > 2.0f) ? 1.0f : 0.0f;

    float vals[11];
    vals[0] = pc;
    vals[1] = pc * gc;
    vals[2] = pe; vals[3] = pm; vals[4] = pj;
    vals[5] = ge; vals[6] = gm; vals[7] = gj;
    vals[8] = pe * ge; vals[9] = pm * gm; vals[10] = pj * gj;

    // bitmask emission: warp == one row of 32 columns
    unsigned pbits = __ballot_sync(0xFFFFFFFFu, pon);
    unsigned gbits = __ballot_sync(0xFFFFFFFFu, gon);
    if (threadIdx.x == 0) {
        g_pmask[b][y][blockIdx.x] = pbits;
        g_gmask[b][y][blockIdx.x] = gbits;
    }

    // block reduction: warp shuffle then across 8 warps in smem
    __shared__ float sm_red[8][11];
#pragma unroll
    for (int k = 0; k < 11; k++) {
        float v = vals[k];
#pragma unroll
        for (int off = 16; off > 0; off >>= 1)
            v += __shfl_down_sync(0xFFFFFFFFu, v, off);
        if (threadIdx.x == 0) sm_red[threadIdx.y][k] = v;
    }
    __syncthreads();
    if (threadIdx.y == 0) {
#pragma unroll
        for (int k = 0; k < 11; k++) {
            float v = (threadIdx.x < 8) ? sm_red[threadIdx.x][k] : 0.0f;
#pragma unroll
            for (int off = 4; off > 0; off >>= 1)
                v += __shfl_down_sync(0xFFFFFFFFu, v, off);
            if (threadIdx.x == 0 && v != 0.0f) atomicAdd(&g_acc[b][k], v);
        }
    }
}

// One block per (batch, direction). dir 0: target=pred, ref=gt (p2g).
// Sum of clamped Chebyshev distances = N_on + sum_{k=1..9} popc(on & ~M_k).
__global__ void __launch_bounds__(1024) k2_dilate() {
    const int b = blockIdx.x >> 1;
    const int dir = blockIdx.x & 1;
    extern __shared__ uint32_t smw[];
    uint32_t* cur = smw;            // 8192 words
    uint32_t* tmp = smw + 8192;     // 8192 words
    uint32_t* tg  = smw + 16384;    // 8192 words

    const uint32_t* ref = (dir == 0) ? &g_gmask[b][0][0] : &g_pmask[b][0][0];
    const uint32_t* tgm = (dir == 0) ? &g_pmask[b][0][0] : &g_gmask[b][0][0];

    const int tid = threadIdx.x;
    unsigned cntN = 0;
    for (int i = tid; i < HH * WPR; i += 1024) {
        cur[i] = ref[i];
        uint32_t t = tgm[i];
        tg[i] = t;
        cntN += __popc(t);
    }
    unsigned accSum = cntN;  // d=1 term: every on-pixel has dist >= 1
    __syncthreads();

    for (int k = 1; k <= 9; k++) {
        // horizontal dilation
        for (int i = tid; i < HH * WPR; i += 1024) {
            int w = i & (WPR - 1);
            uint32_t c = cur[i];
            uint32_t hz = c | (c << 1) | (c >> 1);
            if (w > 0)       hz |= cur[i - 1] >> 31;
            if (w < WPR - 1) hz |= cur[i + 1] << 31;
            tmp[i] = hz;
        }
        __syncthreads();
        // vertical dilation + popcount of uncovered target pixels
        unsigned local = 0;
        for (int i = tid; i < HH * WPR; i += 1024) {
            int r = i >> 4;
            uint32_t v = tmp[i];
            if (r > 0)      v |= tmp[i - WPR];
            if (r < HH - 1) v |= tmp[i + WPR];
            cur[i] = v;
            local += __popc(tg[i] & ~v);
        }
        accSum += local;
        __syncthreads();
    }

    // block reduce accSum and cntN
    __shared__ unsigned redA[32], redB[32];
    unsigned va = accSum, vb = cntN;
#pragma unroll
    for (int off = 16; off > 0; off >>= 1) {
        va += __shfl_down_sync(0xFFFFFFFFu, va, off);
        vb += __shfl_down_sync(0xFFFFFFFFu, vb, off);
    }
    int wid = tid >> 5, lid = tid & 31;
    if (lid == 0) { redA[wid] = va; redB[wid] = vb; }
    __syncthreads();
    if (wid == 0) {
        va = redA[lid];
        vb = redB[lid];
#pragma unroll
        for (int off = 16; off > 0; off >>= 1) {
            va += __shfl_down_sync(0xFFFFFFFFu, va, off);
            vb += __shfl_down_sync(0xFFFFFFFFu, vb, off);
        }
        if (lid == 0) {
            g_acc[b][11 + dir] = (float)va;
            g_acc[b][13 + dir] = (float)vb;
        }
    }
}

__global__ void k3_final(float* __restrict__ out) {
    const int b = threadIdx.x;  // 32 threads
    float a[16];
#pragma unroll
    for (int k = 0; k < 16; k++) a[k] = g_acc[b][k];

    const float Sp = a[0], Spg = a[1];
    const float pec = a[2], pmc = a[3], pjc = a[4];
    const float gec = a[5], gmc = a[6], gjc = a[7];
    const float Ie = a[8], Im = a[9], Ij = a[10];
    const float medP = a[11], medG = a[12], Np = a[13], Ng = a[14];
    const float Sg = Ng;  // gt is exactly {0,1}

    float dice = (2.0f * Spg + 1.0f) / (Sp + Sg + 1.0f);

    float eiou = (Ie + 1.0f) / (pec + gec - Ie + 1.0f);
    float miou = (Im + 1.0f) / (pmc + gmc - Im + 1.0f);
    float jiou = (Ij + 1.0f) / (pjc + gjc - Ij + 1.0f);
    float total = gec + gjc + gmc + 1.0f;
    float sloss = 1.0f - ((gec / total) * eiou + (gjc / total) * jiou + (gmc / total) * miou);

    float p2g = medP / (Np + 1.0f);
    float g2p = medG / (Ng + 1.0f);
    float med = ((p2g + g2p) * 0.5f) / 10.0f;

    // warp means over 32 batches
    float sd = dice, ss = sloss, sme = med;
#pragma unroll
    for (int off = 16; off > 0; off >>= 1) {
        sd  += __shfl_down_sync(0xFFFFFFFFu, sd, off);
        ss  += __shfl_down_sync(0xFFFFFFFFu, ss, off);
        sme += __shfl_down_sync(0xFFFFFFFFu, sme, off);
    }
    if (b == 0) {
        float dice_loss = 1.0f - sd / 32.0f;
        float structural_loss = ss / 32.0f;
        float medial_loss = sme / 32.0f;
        float avg = (dice_loss + structural_loss + medial_loss) / 3.0f;
        float r = dice_loss / (dice_loss + 1.0f) * avg
                + structural_loss / (structural_loss + 1.0f) * avg
                + medial_loss / (medial_loss + 1.0f) * avg;
        out[0] = r;
    }
}

extern "C" void kernel_launch(void* const* d_in, const int* in_sizes, int n_in,
                              void* d_out, int out_size) {
    const float* pred = (const float*)d_in[0];
    const float* gt   = (const float*)d_in[1];
    float* out = (float*)d_out;

    cudaFuncSetAttribute(k2_dilate, cudaFuncAttributeMaxDynamicSharedMemorySize,
                         3 * HH * WPR * sizeof(uint32_t));

    k0_zero<<<1, 512>>>();
    dim3 g1(WW / 32, HH / 8, NB), b1(32, 8);
    k1_pixel<<<g1, b1>>>(pred, gt);
    k2_dilate<<<NB * 2, 1024, 3 * HH * WPR * sizeof(uint32_t)>>>();
    k3_final<<<1, 32>>>(out);
}

// round 3
// speedup vs baseline: 2.2588x; 2.2588x over previous
#include <cuda_runtime.h>
#include <stdint.h>

#define NB 32
#define HH 512
#define WW 512
#define WPR 16  // 512 bits / 32 = 16 words per row

// Accumulator slots per batch:
// 0: S_p   1: S_pg
// 2: pe_c  3: pm_c  4: pj_c  5: ge_c  6: gm_c  7: gj_c
// 8: Ie    9: Im   10: Ij
// 11: medsum_p2g  12: medsum_g2p  13: N_p  14: N_g
__device__ float g_acc[NB][16];
__device__ uint32_t g_pmask[NB][HH][WPR];
__device__ uint32_t g_gmask[NB][HH][WPR];

__global__ void k0_zero() {
    int i = threadIdx.x;
    if (i < NB * 16) ((float*)g_acc)[i] = 0.0f;
}

// Tile: 128 (x) x 16 (y) pixels per block, 512 threads, 4 px/thread along x.
// SMEM tile with 1-px halo, rows padded: cols 3..132 used, 136 allocated.
__global__ void __launch_bounds__(512) k1_pixel(const float* __restrict__ pred,
                                                const float* __restrict__ gt) {
    const int b = blockIdx.z;
    const int bx = blockIdx.x;   // 0..3   (x tile, 128 px each)
    const int by = blockIdx.y;   // 0..31  (y tile, 16 rows each)
    const int tid = threadIdx.x; // 0..511
    const int tx = tid & 31, ty = tid >> 5;

    __shared__ float sp[18][136];
    __shared__ float sg[18][136];
    __shared__ unsigned char nb[16][32];
    __shared__ float sm_red[16][11];

    const size_t base = (size_t)b * (HH * WW);
    const int gx0 = bx * 128;

    // ---- load tile + halo (coalesced float4) ----
    for (int r = ty; r < 18; r += 16) {
        int gy = by * 16 - 1 + r;
        bool yok = ((unsigned)gy < HH);
        size_t rowoff = base + (size_t)gy * WW;
        float4 pv = make_float4(0.f, 0.f, 0.f, 0.f), gv = pv;
        if (yok) {
            pv = __ldg((const float4*)(pred + rowoff + gx0) + tx);
            gv = __ldg((const float4*)(gt   + rowoff + gx0) + tx);
        }
        *(float4*)&sp[r][4 + tx * 4] = pv;
        *(float4*)&sg[r][4 + tx * 4] = gv;
        if (tx == 0) {
            float pl = 0.f, gl = 0.f;
            if (yok && gx0 > 0) {
                pl = __ldg(pred + rowoff + gx0 - 1);
                gl = __ldg(gt   + rowoff + gx0 - 1);
            }
            sp[r][3] = pl; sg[r][3] = gl;
        }
        if (tx == 31) {
            float pr = 0.f, gr = 0.f;
            int gxr = gx0 + 128;
            if (yok && gxr < WW) {
                pr = __ldg(pred + rowoff + gxr);
                gr = __ldg(gt   + rowoff + gxr);
            }
            sp[r][132] = pr; sg[r][132] = gr;
        }
    }
    __syncthreads();

    // ---- stencil: column sums over 3 rows for 6 columns (x-1..x+4) ----
    const int xb = 4 + tx * 4;
    float colp[6] = {0, 0, 0, 0, 0, 0};
    float colg[6] = {0, 0, 0, 0, 0, 0};
    float pc4[4], gc4[4];
#pragma unroll
    for (int r = 0; r < 3; r++) {
        float l = sp[ty + r][xb - 1];
        float4 m = *(const float4*)&sp[ty + r][xb];
        float rr = sp[ty + r][xb + 4];
        colp[0] += l; colp[1] += m.x; colp[2] += m.y;
        colp[3] += m.z; colp[4] += m.w; colp[5] += rr;
        if (r == 1) { pc4[0] = m.x; pc4[1] = m.y; pc4[2] = m.z; pc4[3] = m.w; }
        float gl = sg[ty + r][xb - 1];
        float4 gm = *(const float4*)&sg[ty + r][xb];
        float grr = sg[ty + r][xb + 4];
        colg[0] += gl; colg[1] += gm.x; colg[2] += gm.y;
        colg[3] += gm.z; colg[4] += gm.w; colg[5] += grr;
        if (r == 1) { gc4[0] = gm.x; gc4[1] = gm.y; gc4[2] = gm.z; gc4[3] = gm.w; }
    }

    float vals[11];
#pragma unroll
    for (int k = 0; k < 11; k++) vals[k] = 0.f;
    unsigned pnib = 0, gnib = 0;
#pragma unroll
    for (int j = 0; j < 4; j++) {
        const float pc = pc4[j], gc = gc4[j];
        const bool pon = pc > 0.5f;
        const bool gon = gc > 0.5f;
        const float np = colp[j] + colp[j + 1] + colp[j + 2] - pc;
        const float ng = colg[j] + colg[j + 1] + colg[j + 2] - gc;
        const float pe = (pon && np == 1.0f) ? 1.0f : 0.0f;
        const float pm = (pon && np == 2.0f) ? 1.0f : 0.0f;
        const float pj = (pon && np > 2.0f) ? 1.0f : 0.0f;
        const float ge = (gon && ng == 1.0f) ? 1.0f : 0.0f;
        const float gm = (gon && ng == 2.0f) ? 1.0f : 0.0f;
        const float gj = (gon && ng > 2.0f) ? 1.0f : 0.0f;
        vals[0] += pc;
        vals[1] += pc * gc;
        vals[2] += pe; vals[3] += pm; vals[4] += pj;
        vals[5] += ge; vals[6] += gm; vals[7] += gj;
        vals[8] += pe * ge; vals[9] += pm * gm; vals[10] += pj * gj;
        pnib |= (unsigned)pon << j;
        gnib |= (unsigned)gon << j;
    }
    nb[ty][tx] = (unsigned char)(pnib | (gnib << 4));

    // warp (row) reduction of the 11 accumulators
#pragma unroll
    for (int k = 0; k < 11; k++) {
        float v = vals[k];
#pragma unroll
        for (int off = 16; off > 0; off >>= 1)
            v += __shfl_down_sync(0xFFFFFFFFu, v, off);
        if (tx == 0) sm_red[ty][k] = v;
    }
    __syncthreads();

    // pack nibbles -> 32-bit mask words (16 rows x 4 words per array)
    if (tid < 64) {
        int y = tid >> 2, w = tid & 3;
        unsigned pw = 0, gw = 0;
#pragma unroll
        for (int i = 0; i < 8; i++) {
            unsigned v = nb[y][w * 8 + i];
            pw |= (v & 0xFu) << (4 * i);
            gw |= (v >> 4) << (4 * i);
        }
        g_pmask[b][by * 16 + y][bx * 4 + w] = pw;
        g_gmask[b][by * 16 + y][bx * 4 + w] = gw;
    }

    // block reduction across the 16 row-partials, then atomic
    if (ty == 0) {
#pragma unroll
        for (int k = 0; k < 11; k++) {
            float v = (tx < 16) ? sm_red[tx][k] : 0.0f;
#pragma unroll
            for (int off = 8; off > 0; off >>= 1)
                v += __shfl_down_sync(0xFFFFFFFFu, v, off);
            if (tx == 0 && v != 0.0f) atomicAdd(&g_acc[b][k], v);
        }
    }
}

// One block per (batch, direction). dir 0: target=pred, ref=gt (p2g).
// Sum of clamped Chebyshev distances = N_on + sum_{k=1..9} popc(on & ~M_k).
__global__ void __launch_bounds__(1024) k2_dilate() {
    const int b = blockIdx.x >> 1;
    const int dir = blockIdx.x & 1;
    extern __shared__ uint32_t smw[];
    uint32_t* cur = smw;            // 8192 words
    uint32_t* tmp = smw + 8192;     // 8192 words
    uint32_t* tg  = smw + 16384;    // 8192 words

    const uint32_t* ref = (dir == 0) ? &g_gmask[b][0][0] : &g_pmask[b][0][0];
    const uint32_t* tgm = (dir == 0) ? &g_pmask[b][0][0] : &g_gmask[b][0][0];

    const int tid = threadIdx.x;
    unsigned cntN = 0;
    for (int i = tid; i < HH * WPR; i += 1024) {
        cur[i] = ref[i];
        uint32_t t = tgm[i];
        tg[i] = t;
        cntN += __popc(t);
    }
    unsigned accSum = cntN;  // d=1 term: every on-pixel has dist >= 1
    __syncthreads();

    for (int k = 1; k <= 9; k++) {
        // horizontal dilation
        for (int i = tid; i < HH * WPR; i += 1024) {
            int w = i & (WPR - 1);
            uint32_t c = cur[i];
            uint32_t hz = c | (c << 1) | (c >> 1);
            if (w > 0)       hz |= cur[i - 1] >> 31;
            if (w < WPR - 1) hz |= cur[i + 1] << 31;
            tmp[i] = hz;
        }
        __syncthreads();
        // vertical dilation + popcount of uncovered target pixels
        unsigned local = 0;
        for (int i = tid; i < HH * WPR; i += 1024) {
            int r = i >> 4;
            uint32_t v = tmp[i];
            if (r > 0)      v |= tmp[i - WPR];
            if (r < HH - 1) v |= tmp[i + WPR];
            cur[i] = v;
            local += __popc(tg[i] & ~v);
        }
        accSum += local;
        __syncthreads();
    }

    // block reduce accSum and cntN
    __shared__ unsigned redA[32], redB[32];
    unsigned va = accSum, vb = cntN;
#pragma unroll
    for (int off = 16; off > 0; off >>= 1) {
        va += __shfl_down_sync(0xFFFFFFFFu, va, off);
        vb += __shfl_down_sync(0xFFFFFFFFu, vb, off);
    }
    int wid = tid >> 5, lid = tid & 31;
    if (lid == 0) { redA[wid] = va; redB[wid] = vb; }
    __syncthreads();
    if (wid == 0) {
        va = redA[lid];
        vb = redB[lid];
#pragma unroll
        for (int off = 16; off > 0; off >>= 1) {
            va += __shfl_down_sync(0xFFFFFFFFu, va, off);
            vb += __shfl_down_sync(0xFFFFFFFFu, vb, off);
        }
        if (lid == 0) {
            g_acc[b][11 + dir] = (float)va;
            g_acc[b][13 + dir] = (float)vb;
        }
    }
}

__global__ void k3_final(float* __restrict__ out) {
    const int b = threadIdx.x;  // 32 threads
    float a[16];
#pragma unroll
    for (int k = 0; k < 16; k++) a[k] = g_acc[b][k];

    const float Sp = a[0], Spg = a[1];
    const float pec = a[2], pmc = a[3], pjc = a[4];
    const float gec = a[5], gmc = a[6], gjc = a[7];
    const float Ie = a[8], Im = a[9], Ij = a[10];
    const float medP = a[11], medG = a[12], Np = a[13], Ng = a[14];
    const float Sg = Ng;  // gt is exactly {0,1}

    float dice = (2.0f * Spg + 1.0f) / (Sp + Sg + 1.0f);

    float eiou = (Ie + 1.0f) / (pec + gec - Ie + 1.0f);
    float miou = (Im + 1.0f) / (pmc + gmc - Im + 1.0f);
    float jiou = (Ij + 1.0f) / (pjc + gjc - Ij + 1.0f);
    float total = gec + gjc + gmc + 1.0f;
    float sloss = 1.0f - ((gec / total) * eiou + (gjc / total) * jiou + (gmc / total) * miou);

    float p2g = medP / (Np + 1.0f);
    float g2p = medG / (Ng + 1.0f);
    float med = ((p2g + g2p) * 0.5f) / 10.0f;

    // warp means over 32 batches
    float sd = dice, ss = sloss, sme = med;
#pragma unroll
    for (int off = 16; off > 0; off >>= 1) {
        sd  += __shfl_down_sync(0xFFFFFFFFu, sd, off);
        ss  += __shfl_down_sync(0xFFFFFFFFu, ss, off);
        sme += __shfl_down_sync(0xFFFFFFFFu, sme, off);
    }
    if (b == 0) {
        float dice_loss = 1.0f - sd / 32.0f;
        float structural_loss = ss / 32.0f;
        float medial_loss = sme / 32.0f;
        float avg = (dice_loss + structural_loss + medial_loss) / 3.0f;
        float r = dice_loss / (dice_loss + 1.0f) * avg
                + structural_loss / (structural_loss + 1.0f) * avg
                + medial_loss / (medial_loss + 1.0f) * avg;
        out[0] = r;
    }
}

extern "C" void kernel_launch(void* const* d_in, const int* in_sizes, int n_in,
                              void* d_out, int out_size) {
    const float* pred = (const float*)d_in[0];
    const float* gt   = (const float*)d_in[1];
    float* out = (float*)d_out;

    cudaFuncSetAttribute(k2_dilate, cudaFuncAttributeMaxDynamicSharedMemorySize,
                         3 * HH * WPR * sizeof(uint32_t));

    k0_zero<<<1, 512>>>();
    dim3 g1(WW / 128, HH / 16, NB), b1(512);
    k1_pixel<<<g1, b1>>>(pred, gt);
    k2_dilate<<<NB * 2, 1024, 3 * HH * WPR * sizeof(uint32_t)>>>();
    k3_final<<<1, 32>>>(out);
}

// round 8
// speedup vs baseline: 2.9696x; 1.3147x over previous
#include <cuda_runtime.h>
#include <stdint.h>

#define NB 32
#define HH 512
#define WW 512
#define WPR 16  // 512 bits / 32 = 16 uint32 words per row

// Accumulator slots per batch:
// 0: S_p   1: S_pg
// 2: pe_c  3: pm_c  4: pj_c  5: ge_c  6: gm_c  7: gj_c
// 8: Ie    9: Im   10: Ij
// 11: medpart_p2g  12: medpart_g2p  13: N_p  14: N_g
__device__ float g_acc[NB][16];
__device__ uint32_t g_pmask[NB][HH][WPR];
__device__ uint32_t g_gmask[NB][HH][WPR];

__global__ void k0_zero() {
    int i = threadIdx.x;
    if (i < NB * 16) ((float*)g_acc)[i] = 0.0f;
}

struct Raw { float4 c; float l, r; };

__device__ __forceinline__ Raw load_raw(const float* __restrict__ img, size_t base,
                                        int r, int x0, int lane) {
    Raw o;
    if ((unsigned)r < HH) {
        const float* rp = img + base + (size_t)r * WW;
        o.c = __ldg((const float4*)rp + (x0 >> 2));
        o.l = 0.f; o.r = 0.f;
        if (lane == 0 && x0 > 0) o.l = __ldg(rp + x0 - 1);
        if (lane == 31 && x0 + 4 < WW) o.r = __ldg(rp + x0 + 4);
    } else {
        o.c = make_float4(0.f, 0.f, 0.f, 0.f);
        o.l = 0.f; o.r = 0.f;
    }
    return o;
}

// horizontal triple sums for the 4 pixels of this thread
__device__ __forceinline__ float4 make_h(const Raw& a, int lane) {
    float left  = __shfl_up_sync(0xFFFFFFFFu, a.c.w, 1);
    float right = __shfl_down_sync(0xFFFFFFFFu, a.c.x, 1);
    if (lane == 0)  left = a.l;
    if (lane == 31) right = a.r;
    float4 h;
    h.x = left  + a.c.x + a.c.y;
    h.y = a.c.x + a.c.y + a.c.z;
    h.z = a.c.y + a.c.z + a.c.w;
    h.w = a.c.z + a.c.w + right;
    return h;
}

// Block = 512 threads = 16 warps. Block covers (batch b, x-strip s of 128 cols).
// Warp w handles rows [w*32, w*32+32). Every pixel loaded from HBM exactly once
// (plus 2 halo rows per 32). One row of lookahead hides DRAM latency.
__global__ void __launch_bounds__(512) k1_pixel(const float* __restrict__ pred,
                                                const float* __restrict__ gt) {
    const int tid = threadIdx.x, lane = tid & 31, w = tid >> 5;
    const int b = blockIdx.x >> 2, s = blockIdx.x & 3;
    const int x0 = s * 128 + lane * 4;
    const int r0 = w * 32;
    const size_t base = (size_t)b * (HH * WW);

    Raw prm = load_raw(pred, base, r0 - 1, x0, lane);
    Raw grm = load_raw(gt,   base, r0 - 1, x0, lane);
    Raw pr0 = load_raw(pred, base, r0,     x0, lane);
    Raw gr0 = load_raw(gt,   base, r0,     x0, lane);
    Raw prn = load_raw(pred, base, r0 + 1, x0, lane);
    Raw grn = load_raw(gt,   base, r0 + 1, x0, lane);

    float4 php = make_h(prm, lane), ghp = make_h(grm, lane);
    float4 phc = make_h(pr0, lane), ghc = make_h(gr0, lane);
    float4 pcc = pr0.c, gcc = gr0.c;

    float vals[13];
#pragma unroll
    for (int k = 0; k < 13; k++) vals[k] = 0.f;

    for (int i = 0; i < 32; i++) {
        const int r = r0 + i;
        // prefetch row r+2
        Raw pr2 = load_raw(pred, base, r + 2, x0, lane);
        Raw gr2 = load_raw(gt,   base, r + 2, x0, lane);
        // finish h for row r+1
        float4 phn = make_h(prn, lane), ghn = make_h(grn, lane);

        const float pcv[4] = {pcc.x, pcc.y, pcc.z, pcc.w};
        const float gcv[4] = {gcc.x, gcc.y, gcc.z, gcc.w};
        const float nps[4] = {php.x + phc.x + phn.x, php.y + phc.y + phn.y,
                              php.z + phc.z + phn.z, php.w + phc.w + phn.w};
        const float ngs[4] = {ghp.x + ghc.x + ghn.x, ghp.y + ghc.y + ghn.y,
                              ghp.z + ghc.z + ghn.z, ghp.w + ghc.w + ghn.w};

        unsigned pnib = 0, gnib = 0;
#pragma unroll
        for (int j = 0; j < 4; j++) {
            const float pc = pcv[j], gc = gcv[j];
            const bool pon = pc > 0.5f;
            const bool gon = gc > 0.5f;
            const float np = nps[j] - pc;
            const float ng = ngs[j] - gc;
            const float pe = (pon && np == 1.0f) ? 1.0f : 0.0f;
            const float pm = (pon && np == 2.0f) ? 1.0f : 0.0f;
            const float pj = (pon && np > 2.0f) ? 1.0f : 0.0f;
            const float ge = (gon && ng == 1.0f) ? 1.0f : 0.0f;
            const float gm = (gon && ng == 2.0f) ? 1.0f : 0.0f;
            const float gj = (gon && ng > 2.0f) ? 1.0f : 0.0f;
            vals[0] += pc;
            vals[1] += pc * gc;
            vals[2] += pe; vals[3] += pm; vals[4] += pj;
            vals[5] += ge; vals[6] += gm; vals[7] += gj;
            vals[8] += pe * ge; vals[9] += pm * gm; vals[10] += pj * gj;
            vals[11] += pon ? 1.0f : 0.0f;
            vals[12] += gon ? 1.0f : 0.0f;
            pnib |= (unsigned)pon << j;
            gnib |= (unsigned)gon << j;
        }

        // pack 8 lanes' nibbles into one 32-bit mask word
        const unsigned grpmask = 0xFFu << (lane & 24);
        const unsigned sh = (lane & 7) * 4;
        unsigned pw = __reduce_or_sync(grpmask, pnib << sh);
        unsigned gw = __reduce_or_sync(grpmask, gnib << sh);
        if ((lane & 7) == 0) {
            g_pmask[b][r][s * 4 + (lane >> 3)] = pw;
            g_gmask[b][r][s * 4 + (lane >> 3)] = gw;
        }

        // rotate rolling state
        php = phc; phc = phn; pcc = prn.c; prn = pr2;
        ghp = ghc; ghc = ghn; gcc = grn.c; grn = gr2;
    }

    // warp reduce 13 accumulators, then block reduce in smem, then atomics
    __shared__ float sm_red[16][13];
#pragma unroll
    for (int k = 0; k < 13; k++) {
        float v = vals[k];
#pragma unroll
        for (int off = 16; off > 0; off >>= 1)
            v += __shfl_down_sync(0xFFFFFFFFu, v, off);
        if (lane == 0) sm_red[w][k] = v;
    }
    __syncthreads();
    if (w == 0) {
#pragma unroll
        for (int k = 0; k < 13; k++) {
            float v = (lane < 16) ? sm_red[lane][k] : 0.0f;
#pragma unroll
            for (int off = 8; off > 0; off >>= 1)
                v += __shfl_down_sync(0xFFFFFFFFu, v, off);
            if (lane == 0 && v != 0.0f) {
                int slot = (k < 11) ? k : (k + 2);  // 11->13 (N_p), 12->14 (N_g)
                atomicAdd(&g_acc[b][slot], v);
            }
        }
    }
}

// Medial distance, bit-parallel. One block per (batch, direction, row-chunk).
// dist sum = N_on(target) + sum_{k=1..9} popc(target & ~dilate^k(ref)).
// N_on computed in k1; here we add the 9 uncovered-popcounts on owned rows.
// Influence radius of 9 iterations = 9 rows -> 9-row halos make chunks exact.
#define W64 8            // uint64 words per row
#define MAXR 146         // 128 owned + 2*9 halo
__global__ void __launch_bounds__(256) k2_dilate() {
    const int blk = blockIdx.x;          // 256 = 32 b * 2 dir * 4 chunks
    const int b = blk >> 3;
    const int dir = (blk >> 2) & 1;
    const int ch = blk & 3;
    const int cstart = ch * 128;
    const int rb = (cstart - 9 < 0) ? 0 : cstart - 9;
    const int re = (cstart + 128 + 9 > HH) ? HH : cstart + 128 + 9;
    const int nrows = re - rb;
    const int own0 = cstart - rb;
    const int total = nrows * W64;

    __shared__ uint64_t cur[MAXR * W64];
    __shared__ uint64_t tmp[MAXR * W64];
    __shared__ uint64_t tg[MAXR * W64];

    const uint64_t* ref = (dir == 0) ? (const uint64_t*)&g_gmask[b][rb][0]
                                     : (const uint64_t*)&g_pmask[b][rb][0];
    const uint64_t* tgm = (dir == 0) ? (const uint64_t*)&g_pmask[b][rb][0]
                                     : (const uint64_t*)&g_gmask[b][rb][0];

    const int tid = threadIdx.x;
    for (int i = tid; i < total; i += 256) {
        cur[i] = ref[i];
        tg[i] = tgm[i];
    }
    __syncthreads();

    unsigned acc = 0;
#pragma unroll 1
    for (int k = 1; k <= 9; k++) {
        for (int i = tid; i < total; i += 256) {
            int w = i & (W64 - 1);
            uint64_t c = cur[i];
            uint64_t hz = c | (c << 1) | (c >> 1);
            if (w > 0)       hz |= cur[i - 1] >> 63;
            if (w < W64 - 1) hz |= cur[i + 1] << 63;
            tmp[i] = hz;
        }
        __syncthreads();
        for (int i = tid; i < total; i += 256) {
            int r = i >> 3;
            uint64_t v = tmp[i];
            if (r > 0)         v |= tmp[i - W64];
            if (r < nrows - 1) v |= tmp[i + W64];
            cur[i] = v;
            if (r >= own0 && r < own0 + 128)
                acc += __popcll(tg[i] & ~v);
        }
        __syncthreads();
    }

    // block reduce acc
    __shared__ unsigned redA[8];
    unsigned va = acc;
#pragma unroll
    for (int off = 16; off > 0; off >>= 1)
        va += __shfl_down_sync(0xFFFFFFFFu, va, off);
    int wid = tid >> 5, lid = tid & 31;
    if (lid == 0) redA[wid] = va;
    __syncthreads();
    if (wid == 0) {
        va = (lid < 8) ? redA[lid] : 0u;
#pragma unroll
        for (int off = 4; off > 0; off >>= 1)
            va += __shfl_down_sync(0xFFFFFFFFu, va, off);
        if (lid == 0 && va != 0u)
            atomicAdd(&g_acc[b][11 + dir], (float)va);
    }
}

__global__ void k3_final(float* __restrict__ out) {
    const int b = threadIdx.x;  // 32 threads
    float a[16];
#pragma unroll
    for (int k = 0; k < 16; k++) a[k] = g_acc[b][k];

    const float Sp = a[0], Spg = a[1];
    const float pec = a[2], pmc = a[3], pjc = a[4];
    const float gec = a[5], gmc = a[6], gjc = a[7];
    const float Ie = a[8], Im = a[9], Ij = a[10];
    const float Np = a[13], Ng = a[14];
    const float medP = a[11] + Np;  // + d>=1 term for every on-pixel
    const float medG = a[12] + Ng;
    const float Sg = Ng;  // gt is exactly {0,1}

    float dice = (2.0f * Spg + 1.0f) / (Sp + Sg + 1.0f);

    float eiou = (Ie + 1.0f) / (pec + gec - Ie + 1.0f);
    float miou = (Im + 1.0f) / (pmc + gmc - Im + 1.0f);
    float jiou = (Ij + 1.0f) / (pjc + gjc - Ij + 1.0f);
    float total = gec + gjc + gmc + 1.0f;
    float sloss = 1.0f - ((gec / total) * eiou + (gjc / total) * jiou + (gmc / total) * miou);

    float p2g = medP / (Np + 1.0f);
    float g2p = medG / (Ng + 1.0f);
    float med = ((p2g + g2p) * 0.5f) / 10.0f;

    float sd = dice, ss = sloss, sme = med;
#pragma unroll
    for (int off = 16; off > 0; off >>= 1) {
        sd  += __shfl_down_sync(0xFFFFFFFFu, sd, off);
        ss  += __shfl_down_sync(0xFFFFFFFFu, ss, off);
        sme += __shfl_down_sync(0xFFFFFFFFu, sme, off);
    }
    if (b == 0) {
        float dice_loss = 1.0f - sd / 32.0f;
        float structural_loss = ss / 32.0f;
        float medial_loss = sme / 32.0f;
        float avg = (dice_loss + structural_loss + medial_loss) / 3.0f;
        float r = dice_loss / (dice_loss + 1.0f) * avg
                + structural_loss / (structural_loss + 1.0f) * avg
                + medial_loss / (medial_loss + 1.0f) * avg;
        out[0] = r;
    }
}

extern "C" void kernel_launch(void* const* d_in, const int* in_sizes, int n_in,
                              void* d_out, int out_size) {
    const float* pred = (const float*)d_in[0];
    const float* gt   = (const float*)d_in[1];
    float* out = (float*)d_out;

    k0_zero<<<1, 512>>>();
    k1_pixel<<<NB * 4, 512>>>(pred, gt);   // 128 blocks, one per (batch, x-strip)
    k2_dilate<<<NB * 2 * 4, 256>>>();      // 256 blocks, (batch, dir, row-chunk)
    k3_final<<<1, 32>>>(out);
}

// round 9
// speedup vs baseline: 3.0814x; 1.0376x over previous
#include <cuda_runtime.h>
#include <stdint.h>

#define NB 32
#define HH 512
#define WW 512
#define WPR 16  // 512 bits / 32 = 16 uint32 words per row

// Per-batch final accumulators (written once, by designated K2 blocks):
// 0: S_p 1: S_pg 2..7: pe/pm/pj/ge/gm/gj counts 8..10: Ie/Im/Ij 13: N_p 14: N_g
__device__ float g_acc[NB][16];
// K1 per-block partials: [batch][strip*4+chunk][13]
__device__ float g_part[NB][16][13];
// K2 per-block medial partials: [batch][dir][chunk]
__device__ unsigned g_med[NB][2][4];
__device__ uint32_t g_pmask[NB][HH][WPR];
__device__ uint32_t g_gmask[NB][HH][WPR];
__device__ unsigned g_ticket = 0;

struct Raw { float4 c; float l, r; };

__device__ __forceinline__ Raw load_raw(const float* __restrict__ img, size_t base,
                                        int r, int x0, int lane) {
    Raw o;
    if ((unsigned)r < HH) {
        const float* rp = img + base + (size_t)r * WW;
        o.c = __ldg((const float4*)rp + (x0 >> 2));
        o.l = 0.f; o.r = 0.f;
        if (lane == 0 && x0 > 0) o.l = __ldg(rp + x0 - 1);
        if (lane == 31 && x0 + 4 < WW) o.r = __ldg(rp + x0 + 4);
    } else {
        o.c = make_float4(0.f, 0.f, 0.f, 0.f);
        o.l = 0.f; o.r = 0.f;
    }
    return o;
}

__device__ __forceinline__ float4 make_h(const Raw& a, int lane) {
    float left  = __shfl_up_sync(0xFFFFFFFFu, a.c.w, 1);
    float right = __shfl_down_sync(0xFFFFFFFFu, a.c.x, 1);
    if (lane == 0)  left = a.l;
    if (lane == 31) right = a.r;
    float4 h;
    h.x = left  + a.c.x + a.c.y;
    h.y = a.c.x + a.c.y + a.c.z;
    h.z = a.c.y + a.c.z + a.c.w;
    h.w = a.c.z + a.c.w + right;
    return h;
}

// 512 blocks = (batch, x-strip 0..3, row-chunk 0..3). 256 threads = 8 warps.
// Warp w handles 16 rows. Every pixel loaded from HBM once (+12.5% row halo).
__global__ void __launch_bounds__(256) k1_pixel(const float* __restrict__ pred,
                                                const float* __restrict__ gt) {
    const int tid = threadIdx.x, lane = tid & 31, w = tid >> 5;
    const int blk = blockIdx.x;
    const int b = blk >> 4, s = (blk >> 2) & 3, c = blk & 3;
    const int x0 = s * 128 + lane * 4;
    const int r0 = c * 128 + w * 16;
    const size_t base = (size_t)b * (HH * WW);

    Raw prm = load_raw(pred, base, r0 - 1, x0, lane);
    Raw grm = load_raw(gt,   base, r0 - 1, x0, lane);
    Raw pr0 = load_raw(pred, base, r0,     x0, lane);
    Raw gr0 = load_raw(gt,   base, r0,     x0, lane);
    Raw prn = load_raw(pred, base, r0 + 1, x0, lane);
    Raw grn = load_raw(gt,   base, r0 + 1, x0, lane);

    float4 php = make_h(prm, lane), ghp = make_h(grm, lane);
    float4 phc = make_h(pr0, lane), ghc = make_h(gr0, lane);
    float4 pcc = pr0.c, gcc = gr0.c;

    float vals[11];
#pragma unroll
    for (int k = 0; k < 11; k++) vals[k] = 0.f;
    unsigned cntP = 0, cntG = 0;

    for (int i = 0; i < 16; i++) {
        const int r = r0 + i;
        Raw pr2 = load_raw(pred, base, r + 2, x0, lane);
        Raw gr2 = load_raw(gt,   base, r + 2, x0, lane);
        float4 phn = make_h(prn, lane), ghn = make_h(grn, lane);

        const float pcv[4] = {pcc.x, pcc.y, pcc.z, pcc.w};
        const float gcv[4] = {gcc.x, gcc.y, gcc.z, gcc.w};
        const float nps[4] = {php.x + phc.x + phn.x, php.y + phc.y + phn.y,
                              php.z + phc.z + phn.z, php.w + phc.w + phn.w};
        const float ngs[4] = {ghp.x + ghc.x + ghn.x, ghp.y + ghc.y + ghn.y,
                              ghp.z + ghc.z + ghn.z, ghp.w + ghc.w + ghn.w};

        unsigned pnib = 0, gnib = 0;
#pragma unroll
        for (int j = 0; j < 4; j++) {
            const float pc = pcv[j], gc = gcv[j];
            const bool pon = pc > 0.5f;
            const bool gon = gc > 0.5f;
            const float np = nps[j] - pc;
            const float ng = ngs[j] - gc;
            const float pe = (pon && np == 1.0f) ? 1.0f : 0.0f;
            const float pm = (pon && np == 2.0f) ? 1.0f : 0.0f;
            const float pj = (pon && np > 2.0f) ? 1.0f : 0.0f;
            const float ge = (gon && ng == 1.0f) ? 1.0f : 0.0f;
            const float gm = (gon && ng == 2.0f) ? 1.0f : 0.0f;
            const float gj = (gon && ng > 2.0f) ? 1.0f : 0.0f;
            vals[0] += pc;
            vals[1] += gon ? pc : 0.0f;
            vals[2] += pe; vals[3] += pm; vals[4] += pj;
            vals[5] += ge; vals[6] += gm; vals[7] += gj;
            vals[8] += pe * ge; vals[9] += pm * gm; vals[10] += pj * gj;
            pnib |= (unsigned)pon << j;
            gnib |= (unsigned)gon << j;
        }
        cntP += __popc(pnib);
        cntG += __popc(gnib);

        const unsigned grpmask = 0xFFu << (lane & 24);
        const unsigned sh = (lane & 7) * 4;
        unsigned pw = __reduce_or_sync(grpmask, pnib << sh);
        unsigned gw = __reduce_or_sync(grpmask, gnib << sh);
        if ((lane & 7) == 0) {
            g_pmask[b][r][s * 4 + (lane >> 3)] = pw;
            g_gmask[b][r][s * 4 + (lane >> 3)] = gw;
        }

        php = phc; phc = phn; pcc = prn.c; prn = pr2;
        ghp = ghc; ghc = ghn; gcc = grn.c; grn = gr2;
    }

    // block reduce 13 values -> g_part (no atomics, unique slot per block)
    float v13[13];
#pragma unroll
    for (int k = 0; k < 11; k++) v13[k] = vals[k];
    v13[11] = (float)cntP;
    v13[12] = (float)cntG;

    __shared__ float sm_red[8][13];
#pragma unroll
    for (int k = 0; k < 13; k++) {
        float v = v13[k];
#pragma unroll
        for (int off = 16; off > 0; off >>= 1)
            v += __shfl_down_sync(0xFFFFFFFFu, v, off);
        if (lane == 0) sm_red[w][k] = v;
    }
    __syncthreads();
    if (w == 0) {
#pragma unroll
        for (int k = 0; k < 13; k++) {
            float v = (lane < 8) ? sm_red[lane][k] : 0.0f;
#pragma unroll
            for (int off = 4; off > 0; off >>= 1)
                v += __shfl_down_sync(0xFFFFFFFFu, v, off);
            if (lane == 0) g_part[b][s * 4 + c][k] = v;
        }
    }
}

// 256 blocks = (batch, dir, row-chunk). Bit-parallel dilation in SMEM.
// dist sum = N_on + sum_{k=1..9} popc(target & ~dilate^k(ref)).
// (b, dir=0, ch=0) blocks also fold g_part -> g_acc. Last block to finish
// (ticket) computes the final scalar and resets the ticket.
#define W64 8
#define MAXR 146
__global__ void __launch_bounds__(256) k2_dilate(float* __restrict__ out) {
    const int blk = blockIdx.x;
    const int b = blk >> 3;
    const int dir = (blk >> 2) & 1;
    const int ch = blk & 3;
    const int cstart = ch * 128;
    const int rb = (cstart - 9 < 0) ? 0 : cstart - 9;
    const int re = (cstart + 128 + 9 > HH) ? HH : cstart + 128 + 9;
    const int nrows = re - rb;
    const int own0 = cstart - rb;
    const int total = nrows * W64;

    __shared__ uint64_t cur[MAXR * W64];
    __shared__ uint64_t tmp[MAXR * W64];
    __shared__ uint64_t tg[MAXR * W64];

    const uint64_t* ref = (dir == 0) ? (const uint64_t*)&g_gmask[b][rb][0]
                                     : (const uint64_t*)&g_pmask[b][rb][0];
    const uint64_t* tgm = (dir == 0) ? (const uint64_t*)&g_pmask[b][rb][0]
                                     : (const uint64_t*)&g_gmask[b][rb][0];

    const int tid = threadIdx.x;
    for (int i = tid; i < total; i += 256) {
        cur[i] = ref[i];
        tg[i] = tgm[i];
    }
    __syncthreads();

    unsigned acc = 0;
#pragma unroll 1
    for (int k = 1; k <= 9; k++) {
        for (int i = tid; i < total; i += 256) {
            int w = i & (W64 - 1);
            uint64_t c = cur[i];
            uint64_t hz = c | (c << 1) | (c >> 1);
            if (w > 0)       hz |= cur[i - 1] >> 63;
            if (w < W64 - 1) hz |= cur[i + 1] << 63;
            tmp[i] = hz;
        }
        __syncthreads();
        for (int i = tid; i < total; i += 256) {
            int r = i >> 3;
            uint64_t v = tmp[i];
            if (r > 0)         v |= tmp[i - W64];
            if (r < nrows - 1) v |= tmp[i + W64];
            cur[i] = v;
            if (r >= own0 && r < own0 + 128)
                acc += __popcll(tg[i] & ~v);
        }
        __syncthreads();
    }

    // block reduce acc -> g_med (unique slot)
    __shared__ unsigned redA[8];
    unsigned va = acc;
#pragma unroll
    for (int off = 16; off > 0; off >>= 1)
        va += __shfl_down_sync(0xFFFFFFFFu, va, off);
    int wid = tid >> 5, lid = tid & 31;
    if (lid == 0) redA[wid] = va;
    __syncthreads();
    if (wid == 0) {
        va = (lid < 8) ? redA[lid] : 0u;
#pragma unroll
        for (int off = 4; off > 0; off >>= 1)
            va += __shfl_down_sync(0xFFFFFFFFu, va, off);
        if (lid == 0) g_med[b][dir][ch] = va;
    }

    // designated block folds K1 partials for this batch into g_acc
    if (dir == 0 && ch == 0) {
        __shared__ float sacc[13];
        if (tid < 13) sacc[tid] = 0.f;
        __syncthreads();
        if (tid < 16 * 13) {
            int sc = tid / 13, k = tid % 13;
            atomicAdd(&sacc[k], g_part[b][sc][k]);
        }
        __syncthreads();
        if (tid < 13) {
            int slot = (tid < 11) ? tid : (tid + 2);  // 11->13 (N_p), 12->14 (N_g)
            g_acc[b][slot] = sacc[tid];
        }
    }

    // ticket: last block does the final reduction
    __shared__ bool isLast;
    __threadfence();
    __syncthreads();
    if (tid == 0) {
        unsigned old = atomicAdd(&g_ticket, 1u);
        isLast = (old == (unsigned)(gridDim.x - 1));
        if (isLast) __threadfence();
    }
    __syncthreads();
    if (isLast) {
        if (tid < 32) {
            const int bb = tid;
            float a[16];
#pragma unroll
            for (int k = 0; k < 16; k++) a[k] = g_acc[bb][k];
            const float Sp = a[0], Spg = a[1];
            const float pec = a[2], pmc = a[3], pjc = a[4];
            const float gec = a[5], gmc = a[6], gjc = a[7];
            const float Ie = a[8], Im = a[9], Ij = a[10];
            const float Np = a[13], Ng = a[14];
            unsigned mp = 0, mg = 0;
#pragma unroll
            for (int cc = 0; cc < 4; cc++) {
                mp += g_med[bb][0][cc];
                mg += g_med[bb][1][cc];
            }
            const float medP = (float)mp + Np;
            const float medG = (float)mg + Ng;
            const float Sg = Ng;

            float dice = (2.0f * Spg + 1.0f) / (Sp + Sg + 1.0f);
            float eiou = (Ie + 1.0f) / (pec + gec - Ie + 1.0f);
            float miou = (Im + 1.0f) / (pmc + gmc - Im + 1.0f);
            float jiou = (Ij + 1.0f) / (pjc + gjc - Ij + 1.0f);
            float total3 = gec + gjc + gmc + 1.0f;
            float sloss = 1.0f - ((gec / total3) * eiou + (gjc / total3) * jiou
                                  + (gmc / total3) * miou);
            float p2g = medP / (Np + 1.0f);
            float g2p = medG / (Ng + 1.0f);
            float med = ((p2g + g2p) * 0.5f) / 10.0f;

            float sd = dice, ss = sloss, sme = med;
#pragma unroll
            for (int off = 16; off > 0; off >>= 1) {
                sd  += __shfl_down_sync(0xFFFFFFFFu, sd, off);
                ss  += __shfl_down_sync(0xFFFFFFFFu, ss, off);
                sme += __shfl_down_sync(0xFFFFFFFFu, sme, off);
            }
            if (tid == 0) {
                float dice_loss = 1.0f - sd / 32.0f;
                float structural_loss = ss / 32.0f;
                float medial_loss = sme / 32.0f;
                float avg = (dice_loss + structural_loss + medial_loss) / 3.0f;
                out[0] = dice_loss / (dice_loss + 1.0f) * avg
                       + structural_loss / (structural_loss + 1.0f) * avg
                       + medial_loss / (medial_loss + 1.0f) * avg;
                g_ticket = 0;  // reset for next graph replay
            }
        }
    }
}

extern "C" void kernel_launch(void* const* d_in, const int* in_sizes, int n_in,
                              void* d_out, int out_size) {
    const float* pred = (const float*)d_in[0];
    const float* gt   = (const float*)d_in[1];
    float* out = (float*)d_out;

    k1_pixel<<<NB * 16, 256>>>(pred, gt);     // 512 blocks: (batch, strip, chunk)
    k2_dilate<<<NB * 2 * 4, 256>>>(out);      // 256 blocks: (batch, dir, chunk)
}

// round 11
// speedup vs baseline: 3.1927x; 1.0361x over previous
#include <cuda_runtime.h>
#include <stdint.h>

#define NB 32
#define HH 512
#define WW 512
#define WPR 16   // 512 bits = 16 uint32 words per row
#define OWN 22   // rows owned per k2 warp
#define RPL 10   // rows per lane (4 slots * 10 = 40 = 22 + 2*9 halo)
#define NW 24    // warps per (batch, dir): ceil(512/22)

__device__ uint32_t g_pmask[NB][HH][WPR];
__device__ uint32_t g_gmask[NB][HH][WPR];
__device__ uint32_t g_pe[NB][HH][WPR];
__device__ uint32_t g_pm[NB][HH][WPR];
__device__ uint32_t g_pj[NB][HH][WPR];
// k1 per-block partials: S_p, S_pg, pec, pmc, pjc, N_p, N_g
__device__ float g_part[NB][16][7];
// k2 structural per-warp: gec, gmc, gjc, Ie, Im, Ij
__device__ unsigned g_str[NB][NW][6];
// k2 medial per-warp partial popcounts
__device__ unsigned g_med[NB][2][NW];
__device__ unsigned g_ticket = 0;

struct Raw { float4 c; float l, r; };

__device__ __forceinline__ Raw load_raw(const float* __restrict__ img, size_t base,
                                        int r, int x0, int lane) {
    Raw o;
    if ((unsigned)r < HH) {
        const float* rp = img + base + (size_t)r * WW;
        o.c = __ldg((const float4*)rp + (x0 >> 2));
        o.l = 0.f; o.r = 0.f;
        if (lane == 0 && x0 > 0) o.l = __ldg(rp + x0 - 1);
        if (lane == 31 && x0 + 4 < WW) o.r = __ldg(rp + x0 + 4);
    } else {
        o.c = make_float4(0.f, 0.f, 0.f, 0.f);
        o.l = 0.f; o.r = 0.f;
    }
    return o;
}

__device__ __forceinline__ float4 make_h(const Raw& a, int lane) {
    float left  = __shfl_up_sync(0xFFFFFFFFu, a.c.w, 1);
    float right = __shfl_down_sync(0xFFFFFFFFu, a.c.x, 1);
    if (lane == 0)  left = a.l;
    if (lane == 31) right = a.r;
    float4 h;
    h.x = left  + a.c.x + a.c.y;
    h.y = a.c.x + a.c.y + a.c.z;
    h.z = a.c.y + a.c.z + a.c.w;
    h.w = a.c.z + a.c.w + right;
    return h;
}

// 512 blocks = (batch, x-strip, row-chunk), 256 threads. Pred float stencil +
// mask packing only; all gt structural math moved to k2 (bitwise, exact).
__global__ void __launch_bounds__(256) k1_pixel(const float* __restrict__ pred,
                                                const float* __restrict__ gt) {
    const int tid = threadIdx.x, lane = tid & 31, w8 = tid >> 5;
    const int blk = blockIdx.x;
    const int b = blk >> 4, s = (blk >> 2) & 3, c = blk & 3;
    const int x0 = s * 128 + lane * 4;
    const int r0 = c * 128 + w8 * 16;
    const size_t base = (size_t)b * (HH * WW);

    Raw prm = load_raw(pred, base, r0 - 1, x0, lane);
    Raw pr0 = load_raw(pred, base, r0,     x0, lane);
    Raw prn = load_raw(pred, base, r0 + 1, x0, lane);
    float4 php = make_h(prm, lane), phc = make_h(pr0, lane);
    float4 pcc = pr0.c;
    float4 gcur = __ldg((const float4*)(gt + base + (size_t)r0 * WW + x0));

    float Sp = 0.f, Spg = 0.f;
    unsigned pec = 0, pmc = 0, pjc = 0, cP = 0, cG = 0;

    for (int i = 0; i < 16; i++) {
        const int r = r0 + i;
        Raw pr2 = load_raw(pred, base, r + 2, x0, lane);
        float4 gnx = make_float4(0.f, 0.f, 0.f, 0.f);
        if (r + 1 < HH)
            gnx = __ldg((const float4*)(gt + base + (size_t)(r + 1) * WW + x0));
        float4 phn = make_h(prn, lane);

        const float pcv[4] = {pcc.x, pcc.y, pcc.z, pcc.w};
        const float gcv[4] = {gcur.x, gcur.y, gcur.z, gcur.w};
        const float nps[4] = {php.x + phc.x + phn.x, php.y + phc.y + phn.y,
                              php.z + phc.z + phn.z, php.w + phc.w + phn.w};

        unsigned pn = 0, gn = 0, pen = 0, pmn = 0, pjn = 0;
#pragma unroll
        for (int j = 0; j < 4; j++) {
            const float pc = pcv[j], gc = gcv[j];
            const bool pon = pc > 0.5f;
            const bool gon = gc > 0.5f;
            const float np = nps[j] - pc;
            const bool pe = pon && (np == 1.0f);
            const bool pm = pon && (np == 2.0f);
            const bool pj = pon && (np > 2.0f);
            Sp += pc;
            Spg += gon ? pc : 0.f;
            pn |= (unsigned)pon << j;
            gn |= (unsigned)gon << j;
            pen |= (unsigned)pe << j;
            pmn |= (unsigned)pm << j;
            pjn |= (unsigned)pj << j;
        }
        cP += __popc(pn); cG += __popc(gn);
        pec += __popc(pen); pmc += __popc(pmn); pjc += __popc(pjn);

        const unsigned grpmask = 0xFFu << (lane & 24);
        const unsigned sh = (lane & 7) * 4;
        unsigned pw = __reduce_or_sync(grpmask, pn << sh);
        unsigned gw = __reduce_or_sync(grpmask, gn << sh);
        unsigned ew = __reduce_or_sync(grpmask, pen << sh);
        unsigned mw = __reduce_or_sync(grpmask, pmn << sh);
        unsigned jw = __reduce_or_sync(grpmask, pjn << sh);
        if ((lane & 7) == 0) {
            const int wi = s * 4 + (lane >> 3);
            g_pmask[b][r][wi] = pw;
            g_gmask[b][r][wi] = gw;
            g_pe[b][r][wi] = ew;
            g_pm[b][r][wi] = mw;
            g_pj[b][r][wi] = jw;
        }

        php = phc; phc = phn; pcc = prn.c; prn = pr2; gcur = gnx;
    }

    // block reduce 7 values -> unique g_part slot
    float v7[7] = {Sp, Spg, (float)pec, (float)pmc, (float)pjc, (float)cP, (float)cG};
    __shared__ float sm_red[8][7];
#pragma unroll
    for (int k = 0; k < 7; k++) {
        float v = v7[k];
#pragma unroll
        for (int off = 16; off > 0; off >>= 1)
            v += __shfl_down_sync(0xFFFFFFFFu, v, off);
        if (lane == 0) sm_red[w8][k] = v;
    }
    __syncthreads();
    if (w8 == 0) {
#pragma unroll
        for (int k = 0; k < 7; k++) {
            float v = (lane < 8) ? sm_red[lane][k] : 0.0f;
#pragma unroll
            for (int off = 4; off > 0; off >>= 1)
                v += __shfl_down_sync(0xFFFFFFFFu, v, off);
            if (lane == 0) g_part[b][s * 4 + c][k] = v;
        }
    }
}

__device__ __forceinline__ uint64_t shfl64_up8(uint64_t v) {
    unsigned lo = __shfl_up_sync(0xFFFFFFFFu, (unsigned)v, 8);
    unsigned hi = __shfl_up_sync(0xFFFFFFFFu, (unsigned)(v >> 32), 8);
    return ((uint64_t)hi << 32) | lo;
}
__device__ __forceinline__ uint64_t shfl64_dn8(uint64_t v) {
    unsigned lo = __shfl_down_sync(0xFFFFFFFFu, (unsigned)v, 8);
    unsigned hi = __shfl_down_sync(0xFFFFFFFFu, (unsigned)(v >> 32), 8);
    return ((uint64_t)hi << 32) | lo;
}
__device__ __forceinline__ unsigned warp_red(unsigned v) {
#pragma unroll
    for (int off = 16; off > 0; off >>= 1)
        v += __shfl_down_sync(0xFFFFFFFFu, v, off);
    return v;
}

// 192 blocks = (batch, dir, 3). 8 warps/block; each warp fully autonomous:
// owns 22 rows, loads 40 (9-row halos) as uint64 registers, dilates via
// shuffles with early exit. dir=0 warps also compute gt structural classes
// (bit CSA) + intersections with PE/PM/PJ. Last block folds everything.
__global__ void __launch_bounds__(256) k2_dilate(float* __restrict__ out) {
    const int tid = threadIdx.x, lane = tid & 31, wid = tid >> 5;
    const int blk = blockIdx.x;
    const int b = blk / 6;
    const int rem = blk % 6;
    const int dir = rem / 3;
    const int W = (rem % 3) * 8 + wid;
    const int ownstart = W * OWN;
    const int ownend = (ownstart + OWN > HH) ? HH : ownstart + OWN;
    const int loadstart = ownstart - 9;
    const int w = lane & 7, s = lane >> 3;

    const uint64_t* refm = (dir == 0) ? (const uint64_t*)&g_gmask[b][0][0]
                                      : (const uint64_t*)&g_pmask[b][0][0];
    const uint64_t* tgm  = (dir == 0) ? (const uint64_t*)&g_pmask[b][0][0]
                                      : (const uint64_t*)&g_gmask[b][0][0];

    uint64_t cur[RPL], tg[RPL];
#pragma unroll
    for (int j = 0; j < RPL; j++) {
        int rr = loadstart + s * RPL + j;
        bool in = (unsigned)rr < HH;
        cur[j] = in ? refm[rr * 8 + w] : 0ull;
        bool ow = (rr >= ownstart) && (rr < ownend);
        tg[j] = ow ? tgm[rr * 8 + w] : 0ull;
    }

    // ---- structural (dir=0 only; block-uniform branch) ----
    if (dir == 0) {
        uint64_t cu_m1 = shfl64_up8(cur[RPL - 1]);
        uint64_t cu_p1 = shfl64_dn8(cur[0]);
        if (s == 0) cu_m1 = 0ull;
        if (s == 3) cu_p1 = 0ull;
        unsigned gec = 0, gmc = 0, gjc = 0, Ie = 0, Im = 0, Ij = 0;
#pragma unroll
        for (int j = 0; j < RPL; j++) {
            uint64_t ra = (j > 0) ? cur[j - 1] : cu_m1;
            uint64_t rb = cur[j];
            uint64_t rc = (j < RPL - 1) ? cur[j + 1] : cu_p1;
            // horizontal funnels (left/right neighbor bits via lane shuffles)
            uint64_t rows[3] = {ra, rb, rc};
            uint64_t fl[3], fr[3];
#pragma unroll
            for (int t = 0; t < 3; t++) {
                unsigned hb = (unsigned)(rows[t] >> 63);
                unsigned lb = (unsigned)rows[t] & 1u;
                unsigned vfl = __shfl_up_sync(0xFFFFFFFFu, hb, 1);
                unsigned vfr = __shfl_down_sync(0xFFFFFFFFu, lb, 1);
                fl[t] = (rows[t] << 1) | (w > 0 ? (uint64_t)vfl : 0ull);
                fr[t] = (rows[t] >> 1) | (w < 7 ? ((uint64_t)vfr) << 63 : 0ull);
            }
            int rr = loadstart + s * RPL + j;
            if (rr >= ownstart && rr < ownend) {
                // bit-sliced counter of 8 neighbor inputs: c0,c1 + sticky >=4
                uint64_t in8[8] = {fl[0], ra, fr[0], fl[1], fr[1], fl[2], rc, fr[2]};
                uint64_t c0 = 0, c1 = 0, ge4 = 0;
#pragma unroll
                for (int t = 0; t < 8; t++) {
                    uint64_t car = c0 & in8[t];
                    c0 ^= in8[t];
                    uint64_t car2 = c1 & car;
                    c1 ^= car;
                    ge4 |= car2;
                }
                uint64_t g = rb;
                uint64_t geW = g & c0 & ~c1 & ~ge4;
                uint64_t gmW = g & ~c0 & c1 & ~ge4;
                uint64_t gjW = g & (ge4 | (c0 & c1));
                gec += __popcll(geW); gmc += __popcll(gmW); gjc += __popcll(gjW);
                uint64_t peW = ((const uint64_t*)&g_pe[b][0][0])[rr * 8 + w];
                uint64_t pmW = ((const uint64_t*)&g_pm[b][0][0])[rr * 8 + w];
                uint64_t pjW = ((const uint64_t*)&g_pj[b][0][0])[rr * 8 + w];
                Ie += __popcll(geW & peW);
                Im += __popcll(gmW & pmW);
                Ij += __popcll(gjW & pjW);
            }
        }
        unsigned sr[6] = {gec, gmc, gjc, Ie, Im, Ij};
#pragma unroll
        for (int t = 0; t < 6; t++) {
            unsigned v = warp_red(sr[t]);
            if (lane == 0) g_str[b][W][t] = v;
        }
    }

    // ---- dilation with early exit ----
    unsigned acc = 0;
    uint64_t hz[RPL];
#pragma unroll 1
    for (int k = 1; k <= 9; k++) {
#pragma unroll
        for (int j = 0; j < RPL; j++) {
            unsigned hb = (unsigned)(cur[j] >> 63);
            unsigned lb = (unsigned)cur[j] & 1u;
            unsigned vfl = __shfl_up_sync(0xFFFFFFFFu, hb, 1);
            unsigned vfr = __shfl_down_sync(0xFFFFFFFFu, lb, 1);
            hz[j] = cur[j] | (cur[j] << 1) | (cur[j] >> 1)
                  | (w > 0 ? (uint64_t)vfl : 0ull)
                  | (w < 7 ? ((uint64_t)vfr) << 63 : 0ull);
        }
        uint64_t hz_m1 = shfl64_up8(hz[RPL - 1]);
        uint64_t hz_p1 = shfl64_dn8(hz[0]);
        if (s == 0) hz_m1 = 0ull;
        if (s == 3) hz_p1 = 0ull;
        uint64_t un = 0;
#pragma unroll
        for (int j = 0; j < RPL; j++) {
            uint64_t v = hz[j] | ((j > 0) ? hz[j - 1] : hz_m1)
                               | ((j < RPL - 1) ? hz[j + 1] : hz_p1);
            cur[j] = v;
            uint64_t u = tg[j] & ~v;
            un |= u;
            acc += (unsigned)__popcll(u);
        }
        if (!__any_sync(0xFFFFFFFFu, un != 0ull)) break;
    }
    {
        unsigned v = warp_red(acc);
        if (lane == 0) g_med[b][dir][W] = v;
    }

    // ---- ticket: last block computes the final scalar ----
    __shared__ bool isLast;
    __threadfence();
    __syncthreads();
    if (tid == 0) {
        unsigned old = atomicAdd(&g_ticket, 1u);
        isLast = (old == (unsigned)(gridDim.x - 1));
        if (isLast) __threadfence();
    }
    __syncthreads();
    if (!isLast) return;

    // fold partials: thread (fb, grp) sums its share into smem
    __shared__ float smf[32][8][15];
    {
        const int fb = tid >> 3, grp = tid & 7;
        float part[15];
#pragma unroll
        for (int k = 0; k < 15; k++) part[k] = 0.f;
#pragma unroll
        for (int q = 0; q < 2; q++) {
            int sc = grp * 2 + q;
#pragma unroll
            for (int k = 0; k < 7; k++) part[k] += g_part[fb][sc][k];
        }
#pragma unroll
        for (int q = 0; q < 3; q++) {
            int Wq = grp * 3 + q;
#pragma unroll
            for (int k = 0; k < 6; k++) part[7 + k] += (float)g_str[fb][Wq][k];
            part[13] += (float)g_med[fb][0][Wq];
            part[14] += (float)g_med[fb][1][Wq];
        }
#pragma unroll
        for (int k = 0; k < 15; k++) smf[fb][grp][k] = part[k];
    }
    __syncthreads();
    if (tid < 32) {
        const int bb = tid;
        float a[15];
#pragma unroll
        for (int k = 0; k < 15; k++) {
            float v = 0.f;
#pragma unroll
            for (int g2 = 0; g2 < 8; g2++) v += smf[bb][g2][k];
            a[k] = v;
        }
        const float Sp = a[0], Spg = a[1];
        const float pec = a[2], pmc = a[3], pjc = a[4];
        const float Np = a[5], Ng = a[6];
        const float gec = a[7], gmc = a[8], gjc = a[9];
        const float Ie = a[10], Im = a[11], Ij = a[12];
        const float medP = a[13] + Np;  // + d>=1 term for every on-pixel
        const float medG = a[14] + Ng;
        const float Sg = Ng;

        float dice = (2.0f * Spg + 1.0f) / (Sp + Sg + 1.0f);
        float eiou = (Ie + 1.0f) / (pec + gec - Ie + 1.0f);
        float miou = (Im + 1.0f) / (pmc + gmc - Im + 1.0f);
        float jiou = (Ij + 1.0f) / (pjc + gjc - Ij + 1.0f);
        float total3 = gec + gjc + gmc + 1.0f;
        float sloss = 1.0f - ((gec / total3) * eiou + (gjc / total3) * jiou
                              + (gmc / total3) * miou);
        float p2g = medP / (Np + 1.0f);
        float g2p = medG / (Ng + 1.0f);
        float med = ((p2g + g2p) * 0.5f) / 10.0f;

        float sd = dice, ss = sloss, sme = med;
#pragma unroll
        for (int off = 16; off > 0; off >>= 1) {
            sd  += __shfl_down_sync(0xFFFFFFFFu, sd, off);
            ss  += __shfl_down_sync(0xFFFFFFFFu, ss, off);
            sme += __shfl_down_sync(0xFFFFFFFFu, sme, off);
        }
        if (tid == 0) {
            float dice_loss = 1.0f - sd / 32.0f;
            float structural_loss = ss / 32.0f;
            float medial_loss = sme / 32.0f;
            float avg = (dice_loss + structural_loss + medial_loss) / 3.0f;
            out[0] = dice_loss / (dice_loss + 1.0f) * avg
                   + structural_loss / (structural_loss + 1.0f) * avg
                   + medial_loss / (medial_loss + 1.0f) * avg;
            g_ticket = 0;  // reset for next graph replay
        }
    }
}

extern "C" void kernel_launch(void* const* d_in, const int* in_sizes, int n_in,
                              void* d_out, int out_size) {
    const float* pred = (const float*)d_in[0];
    const float* gt   = (const float*)d_in[1];
    float* out = (float*)d_out;

    k1_pixel<<<NB * 16, 256>>>(pred, gt);   // 512 blocks: (batch, strip, chunk)
    k2_dilate<<<NB * 6, 256>>>(out);        // 192 blocks: (batch, dir, third)
}